// round 3
// baseline (speedup 1.0000x reference)
#include <cuda_runtime.h>
#include <cstdint>

#define SS 7
#define NC 20
#define PREDC 30                    // NC + 10
#define TGTC  25                    // NC + 5
#define BATCH 16384
#define CELLS (BATCH * SS * SS)     // 802816
#define CPB 128                     // cells per tile (= threads per block)
#define NTILES (CELLS / CPB)        // 6272
#define PF4 (CPB * PREDC / 4)       // 960 float4 per tile (pred)
#define TF4 (CPB * TGTC / 4)        // 800 float4 per tile (tgt)
#define STAGE_F4 (PF4 + TF4)        // 1760 float4 = 28160 B per stage
#define NSTAGE 2
#define SMEM_BYTES (NSTAGE * STAGE_F4 * 16)   // 56320 B
#define NBLK 444                    // 3 blocks/SM * 148 SMs

__device__ __forceinline__ void cp16(uint32_t saddr, const void* gptr) {
    asm volatile("cp.async.cg.shared.global [%0], [%1], 16;\n"
                 :: "r"(saddr), "l"(gptr));
}
__device__ __forceinline__ void cp_commit() {
    asm volatile("cp.async.commit_group;\n" ::: "memory");
}
__device__ __forceinline__ void cp_wait1() {
    asm volatile("cp.async.wait_group 1;\n" ::: "memory");
}

__device__ __forceinline__ float iou_fn(float ax, float ay, float aw, float ah,
                                        float bx, float by, float bw, float bh) {
    float ax1 = ax - aw * 0.5f, ax2 = ax + aw * 0.5f;
    float ay1 = ay - ah * 0.5f, ay2 = ay + ah * 0.5f;
    float bx1 = bx - bw * 0.5f, bx2 = bx + bw * 0.5f;
    float by1 = by - bh * 0.5f, by2 = by + bh * 0.5f;
    float iw = fminf(ax2, bx2) - fmaxf(ax1, bx1); iw = fmaxf(iw, 0.0f);
    float ih = fminf(ay2, by2) - fmaxf(ay1, by1); ih = fmaxf(ih, 0.0f);
    float inter = iw * ih;
    float area_a = fabsf(aw * ah);
    float area_b = fabsf(bw * bh);
    return inter / (area_a + area_b - inter + 1e-6f);
}

// Issue async copies for one tile into stage buffer.
__device__ __forceinline__ void issue_tile(uint32_t sbase,
                                           const float4* __restrict__ pred4,
                                           const float4* __restrict__ tgt4,
                                           int tile, int tid) {
    const float4* pg = pred4 + (size_t)tile * PF4;
    const float4* tg = tgt4  + (size_t)tile * TF4;
    uint32_t sp = sbase;                 // pred region
    uint32_t st = sbase + PF4 * 16;      // tgt region
    #pragma unroll
    for (int k = 0; k < PF4 / CPB; k++)                 // 7 full rounds
        cp16(sp + (tid + k * CPB) * 16, pg + tid + k * CPB);
    if (tid < PF4 - (PF4 / CPB) * CPB)                  // 64 remainder
        cp16(sp + (tid + (PF4 / CPB) * CPB) * 16, pg + tid + (PF4 / CPB) * CPB);
    #pragma unroll
    for (int k = 0; k < TF4 / CPB; k++)                 // 6 full rounds
        cp16(st + (tid + k * CPB) * 16, tg + tid + k * CPB);
    if (tid < TF4 - (TF4 / CPB) * CPB)                  // 32 remainder
        cp16(st + (tid + (TF4 / CPB) * CPB) * 16, tg + tid + (TF4 / CPB) * CPB);
}

__device__ __forceinline__ float compute_tile(const float* __restrict__ stage, int tid) {
    const float* p = stage + tid * PREDC;
    const float* t = stage + CPB * PREDC + tid * TGTC;

    float cls = 0.0f;
    #pragma unroll
    for (int c = 0; c < NC; c++) {
        float d = p[c] - t[c];
        cls = fmaf(d, d, cls);
    }

    float b1x = p[20], b1y = p[21], b1w = p[22], b1h = p[23], b1c = p[24];
    float b2x = p[25], b2y = p[26], b2w = p[27], b2h = p[28], b2c = p[29];
    // tb = targets[..., C:C+5] -> channels 20..24 (channel 20 is also the obj flag)
    float tx = t[20], ty = t[21], tw = t[22], th = t[23], tc = t[24];
    float obj = (t[20] == 1.0f) ? 1.0f : 0.0f;

    float iou1 = iou_fn(b1x, b1y, b1w, b1h, tx, ty, tw, th);
    float iou2 = iou_fn(b2x, b2y, b2w, b2h, tx, ty, tw, th);
    bool use1 = iou1 > iou2;

    float rx = use1 ? b1x : b2x;
    float ry = use1 ? b1y : b2y;
    float rw = use1 ? b1w : b2w;
    float rh = use1 ? b1h : b2h;
    float rc = use1 ? b1c : b2c;
    float other_conf = use1 ? b2c : b1c;

    float srw = sqrtf(fmaxf(rw, 1e-6f));
    float srh = sqrtf(fmaxf(rh, 1e-6f));
    float stw = sqrtf(fmaxf(tw, 1e-6f));
    float sth = sqrtf(fmaxf(th, 1e-6f));

    float dx = rx - tx, dy = ry - ty, dw = srw - stw, dh = srh - sth;
    float coord = 5.0f * (dx * dx + dy * dy + dw * dw + dh * dh);
    float dc = rc - tc;
    float obj_conf = dc * dc;
    float noobj_in  = 0.5f * other_conf * other_conf;
    float noobj_out = 0.5f * (b1c * b1c + b2c * b2c);

    return obj * (coord + obj_conf + cls + noobj_in) + (1.0f - obj) * noobj_out;
}

__global__ __launch_bounds__(CPB)
void yolo_loss_kernel(const float4* __restrict__ pred4,
                      const float4* __restrict__ tgt4,
                      float* __restrict__ out) {
    extern __shared__ __align__(16) float smem[];
    __shared__ float warp_sums[CPB / 32];

    const int tid = threadIdx.x;
    const int bid = blockIdx.x;
    uint32_t sbase = (uint32_t)__cvta_generic_to_shared(smem);

    // Balanced contiguous partition of tiles across blocks.
    const int q = NTILES / NBLK;           // 14
    const int r = NTILES % NBLK;           // 56
    const int start = bid * q + (bid < r ? bid : r);
    const int nt = q + (bid < r ? 1 : 0);

    // Prologue: fill both stages.
    issue_tile(sbase + 0 * STAGE_F4 * 16, pred4, tgt4, start + 0, tid);
    cp_commit();                                           // G0
    if (nt > 1) issue_tile(sbase + 1 * STAGE_F4 * 16, pred4, tgt4, start + 1, tid);
    cp_commit();                                           // G1

    float acc = 0.0f;
    for (int i = 0; i < nt; i++) {
        cp_wait1();            // group for tile i complete (tile i+1 may be in flight)
        __syncthreads();
        const int s = i & 1;
        acc += compute_tile(smem + s * STAGE_F4 * 4, tid);
        __syncthreads();       // everyone done reading stage s before refill
        if (i + 2 < nt)
            issue_tile(sbase + s * STAGE_F4 * 16, pred4, tgt4, start + i + 2, tid);
        cp_commit();           // G_{i+2} (possibly empty — keeps group count aligned)
    }

    // Block reduce + single atomic.
    #pragma unroll
    for (int off = 16; off > 0; off >>= 1)
        acc += __shfl_xor_sync(0xFFFFFFFFu, acc, off);
    int lane = tid & 31, wid = tid >> 5;
    if (lane == 0) warp_sums[wid] = acc;
    __syncthreads();
    if (tid == 0) {
        float s = 0.0f;
        #pragma unroll
        for (int w = 0; w < CPB / 32; w++) s += warp_sums[w];
        atomicAdd(out, s * (1.0f / (float)BATCH));
    }
}

extern "C" void kernel_launch(void* const* d_in, const int* in_sizes, int n_in,
                              void* d_out, int out_size) {
    const float4* pred4 = (const float4*)d_in[0];
    const float4* tgt4  = (const float4*)d_in[1];
    float* out = (float*)d_out;
    cudaFuncSetAttribute(yolo_loss_kernel,
                         cudaFuncAttributeMaxDynamicSharedMemorySize, SMEM_BYTES);
    cudaMemsetAsync(out, 0, sizeof(float));
    yolo_loss_kernel<<<NBLK, CPB, SMEM_BYTES>>>(pred4, tgt4, out);
}

// round 5
// speedup vs baseline: 1.0182x; 1.0182x over previous
#include <cuda_runtime.h>
#include <cstdint>

#define SS 7
#define NC 20
#define PREDC 30                    // NC + 10
#define TGTC  25                    // NC + 5
#define BATCH 16384
#define CELLS (BATCH * SS * SS)     // 802816
#define CPB 128                     // cells per tile (= threads per block)
#define NTILES (CELLS / CPB)        // 6272
#define PF4 (CPB * PREDC / 4)       // 960 float4 per tile (pred)
#define TF4 (CPB * TGTC / 4)        // 800 float4 per tile (tgt)
#define STAGE_F4 (PF4 + TF4)        // 1760 float4 = 28160 B per stage
#define NSTAGE 4
#define SMEM_BYTES (NSTAGE * STAGE_F4 * 16)   // 112640 B
#define NBLK 296                    // 2 blocks/SM * 148 SMs

__device__ __forceinline__ void cp16(uint32_t saddr, const void* gptr) {
    asm volatile("cp.async.cg.shared.global [%0], [%1], 16;\n"
                 :: "r"(saddr), "l"(gptr));
}
__device__ __forceinline__ void cp_commit() {
    asm volatile("cp.async.commit_group;\n" ::: "memory");
}
__device__ __forceinline__ void cp_wait2() {
    asm volatile("cp.async.wait_group 2;\n" ::: "memory");
}

__device__ __forceinline__ float iou_fn(float ax, float ay, float aw, float ah,
                                        float bx, float by, float bw, float bh) {
    float ax1 = ax - aw * 0.5f, ax2 = ax + aw * 0.5f;
    float ay1 = ay - ah * 0.5f, ay2 = ay + ah * 0.5f;
    float bx1 = bx - bw * 0.5f, bx2 = bx + bw * 0.5f;
    float by1 = by - bh * 0.5f, by2 = by + bh * 0.5f;
    float iw = fminf(ax2, bx2) - fmaxf(ax1, bx1); iw = fmaxf(iw, 0.0f);
    float ih = fminf(ay2, by2) - fmaxf(ay1, by1); ih = fmaxf(ih, 0.0f);
    float inter = iw * ih;
    float area_a = fabsf(aw * ah);
    float area_b = fabsf(bw * bh);
    return inter / (area_a + area_b - inter + 1e-6f);
}

// Issue async copies for one tile into the given stage buffer.
__device__ __forceinline__ void issue_tile(uint32_t sbase,
                                           const float4* __restrict__ pred4,
                                           const float4* __restrict__ tgt4,
                                           int tile, int tid) {
    const float4* pg = pred4 + (size_t)tile * PF4;
    const float4* tg = tgt4  + (size_t)tile * TF4;
    uint32_t sp = sbase;                 // pred region
    uint32_t st = sbase + PF4 * 16;      // tgt region
    #pragma unroll
    for (int k = 0; k < PF4 / CPB; k++)                 // 7 full rounds
        cp16(sp + (tid + k * CPB) * 16, pg + tid + k * CPB);
    if (tid < PF4 - (PF4 / CPB) * CPB)                  // 64 remainder
        cp16(sp + (tid + (PF4 / CPB) * CPB) * 16, pg + tid + (PF4 / CPB) * CPB);
    #pragma unroll
    for (int k = 0; k < TF4 / CPB; k++)                 // 6 full rounds
        cp16(st + (tid + k * CPB) * 16, tg + tid + k * CPB);
    if (tid < TF4 - (TF4 / CPB) * CPB)                  // 32 remainder
        cp16(st + (tid + (TF4 / CPB) * CPB) * 16, tg + tid + (TF4 / CPB) * CPB);
}

__device__ __forceinline__ float compute_tile(const float* __restrict__ stage, int tid) {
    const float* p = stage + tid * PREDC;
    const float* t = stage + CPB * PREDC + tid * TGTC;

    float cls = 0.0f;
    #pragma unroll
    for (int c = 0; c < NC; c++) {
        float d = p[c] - t[c];
        cls = fmaf(d, d, cls);
    }

    float b1x = p[20], b1y = p[21], b1w = p[22], b1h = p[23], b1c = p[24];
    float b2x = p[25], b2y = p[26], b2w = p[27], b2h = p[28], b2c = p[29];
    // tb = targets[..., C:C+5] -> channels 20..24 (channel 20 doubles as obj flag)
    float tx = t[20], ty = t[21], tw = t[22], th = t[23], tc = t[24];
    float obj = (t[20] == 1.0f) ? 1.0f : 0.0f;

    float iou1 = iou_fn(b1x, b1y, b1w, b1h, tx, ty, tw, th);
    float iou2 = iou_fn(b2x, b2y, b2w, b2h, tx, ty, tw, th);
    bool use1 = iou1 > iou2;

    float rx = use1 ? b1x : b2x;
    float ry = use1 ? b1y : b2y;
    float rw = use1 ? b1w : b2w;
    float rh = use1 ? b1h : b2h;
    float rc = use1 ? b1c : b2c;
    float other_conf = use1 ? b2c : b1c;

    float srw = sqrtf(fmaxf(rw, 1e-6f));
    float srh = sqrtf(fmaxf(rh, 1e-6f));
    float stw = sqrtf(fmaxf(tw, 1e-6f));
    float sth = sqrtf(fmaxf(th, 1e-6f));

    float dx = rx - tx, dy = ry - ty, dw = srw - stw, dh = srh - sth;
    float coord = 5.0f * (dx * dx + dy * dy + dw * dw + dh * dh);
    float dc = rc - tc;
    float obj_conf = dc * dc;
    float noobj_in  = 0.5f * other_conf * other_conf;
    float noobj_out = 0.5f * (b1c * b1c + b2c * b2c);

    return obj * (coord + obj_conf + cls + noobj_in) + (1.0f - obj) * noobj_out;
}

__global__ __launch_bounds__(CPB)
void yolo_loss_kernel(const float4* __restrict__ pred4,
                      const float4* __restrict__ tgt4,
                      float* __restrict__ out) {
    extern __shared__ __align__(16) float smem[];
    __shared__ float warp_sums[CPB / 32];

    const int tid = threadIdx.x;
    const int bid = blockIdx.x;
    uint32_t sbase = (uint32_t)__cvta_generic_to_shared(smem);

    // Balanced contiguous partition of tiles across blocks.
    const int q = NTILES / NBLK;           // 21
    const int r = NTILES % NBLK;           // 56
    const int start = bid * q + (bid < r ? bid : r);
    const int nt = q + (bid < r ? 1 : 0);  // 21 or 22 (always >= NSTAGE-1)

    // Prologue: fill stages 0..2 (depth-3 prefetch).
    #pragma unroll
    for (int s = 0; s < NSTAGE - 1; s++) {
        if (s < nt)
            issue_tile(sbase + s * STAGE_F4 * 16, pred4, tgt4, start + s, tid);
        cp_commit();
    }

    float acc = 0.0f;
    for (int i = 0; i < nt; i++) {
        cp_wait2();            // tile i's group complete (i+1, i+2 may be pending)
        __syncthreads();       // all threads done reading slot (i+3)&3 (tile i-1)
        // Refill FIRST (into the slot freed by tile i-1), so LDGSTS issue
        // overlaps this tile's compute instead of trailing it.
        if (i + NSTAGE - 1 < nt)
            issue_tile(sbase + ((i + NSTAGE - 1) & (NSTAGE - 1)) * STAGE_F4 * 16,
                       pred4, tgt4, start + i + NSTAGE - 1, tid);
        cp_commit();
        acc += compute_tile(smem + (i & (NSTAGE - 1)) * STAGE_F4 * 4, tid);
    }

    // Block reduce + single atomic.
    #pragma unroll
    for (int off = 16; off > 0; off >>= 1)
        acc += __shfl_xor_sync(0xFFFFFFFFu, acc, off);
    int lane = tid & 31, wid = tid >> 5;
    if (lane == 0) warp_sums[wid] = acc;
    __syncthreads();
    if (tid == 0) {
        float s = 0.0f;
        #pragma unroll
        for (int w = 0; w < CPB / 32; w++) s += warp_sums[w];
        atomicAdd(out, s * (1.0f / (float)BATCH));
    }
}

extern "C" void kernel_launch(void* const* d_in, const int* in_sizes, int n_in,
                              void* d_out, int out_size) {
    const float4* pred4 = (const float4*)d_in[0];
    const float4* tgt4  = (const float4*)d_in[1];
    float* out = (float*)d_out;
    cudaFuncSetAttribute(yolo_loss_kernel,
                         cudaFuncAttributeMaxDynamicSharedMemorySize, SMEM_BYTES);
    cudaMemsetAsync(out, 0, sizeof(float));
    yolo_loss_kernel<<<NBLK, CPB, SMEM_BYTES>>>(pred4, tgt4, out);
}

// round 6
// speedup vs baseline: 1.0604x; 1.0415x over previous
#include <cuda_runtime.h>
#include <cstdint>

#define SS 7
#define NC 20
#define PREDC 30                    // NC + 10
#define TGTC  25                    // NC + 5
#define BATCH 16384
#define CELLS (BATCH * SS * SS)     // 802816
#define CPB 128                     // cells per tile (= threads per block)
#define NTILES (CELLS / CPB)        // 6272
#define PRED_TILE_B (CPB * PREDC * 4)   // 15360 B
#define TGT_TILE_B  (CPB * TGTC * 4)    // 12800 B
#define STAGE_B (PRED_TILE_B + TGT_TILE_B)  // 28160 B
#define NSTAGE 4
#define SMEM_BYTES (NSTAGE * STAGE_B)   // 112640 B
#define NBLK 296                    // 2 blocks/SM * 148 SMs

// ---- TMA bulk copy + mbarrier primitives ----
__device__ __forceinline__ void bulk_g2s(uint32_t dst_smem, const void* src,
                                         uint32_t bytes, uint32_t mbar) {
    asm volatile(
        "cp.async.bulk.shared::cluster.global.mbarrier::complete_tx::bytes "
        "[%0], [%1], %2, [%3];\n"
        :: "r"(dst_smem), "l"(src), "r"(bytes), "r"(mbar) : "memory");
}
__device__ __forceinline__ void mbar_init(uint32_t mbar, uint32_t count) {
    asm volatile("mbarrier.init.shared.b64 [%0], %1;\n" :: "r"(mbar), "r"(count) : "memory");
}
__device__ __forceinline__ void mbar_expect_tx(uint32_t mbar, uint32_t bytes) {
    asm volatile("mbarrier.arrive.expect_tx.shared.b64 _, [%0], %1;\n"
                 :: "r"(mbar), "r"(bytes) : "memory");
}
__device__ __forceinline__ void mbar_wait(uint32_t mbar, uint32_t parity) {
    uint32_t done;
    asm volatile(
        "{\n\t.reg .pred p;\n\t"
        "mbarrier.try_wait.parity.acquire.cta.shared::cta.b64 p, [%1], %2;\n\t"
        "selp.b32 %0, 1, 0, p;\n\t}"
        : "=r"(done) : "r"(mbar), "r"(parity) : "memory");
    if (!done) {
        asm volatile(
            "{\n\t.reg .pred P1;\n\t"
            "WAIT_LOOP_%=:\n\t"
            "mbarrier.try_wait.parity.acquire.cta.shared::cta.b64 P1, [%0], %1, 0x989680;\n\t"
            "@P1 bra.uni WAIT_DONE_%=;\n\t"
            "bra.uni WAIT_LOOP_%=;\n\t"
            "WAIT_DONE_%=:\n\t}"
            :: "r"(mbar), "r"(parity) : "memory");
    }
}

__device__ __forceinline__ float iou_fn(float ax, float ay, float aw, float ah,
                                        float bx, float by, float bw, float bh) {
    float ax1 = ax - aw * 0.5f, ax2 = ax + aw * 0.5f;
    float ay1 = ay - ah * 0.5f, ay2 = ay + ah * 0.5f;
    float bx1 = bx - bw * 0.5f, bx2 = bx + bw * 0.5f;
    float by1 = by - bh * 0.5f, by2 = by + bh * 0.5f;
    float iw = fminf(ax2, bx2) - fmaxf(ax1, bx1); iw = fmaxf(iw, 0.0f);
    float ih = fminf(ay2, by2) - fmaxf(ay1, by1); ih = fmaxf(ih, 0.0f);
    float inter = iw * ih;
    float area_a = fabsf(aw * ah);
    float area_b = fabsf(bw * bh);
    return inter / (area_a + area_b - inter + 1e-6f);
}

__device__ __forceinline__ float compute_tile(const float* __restrict__ stage, int tid) {
    const float* p = stage + tid * PREDC;
    const float* t = stage + CPB * PREDC + tid * TGTC;

    float cls = 0.0f;
    #pragma unroll
    for (int c = 0; c < NC; c++) {
        float d = p[c] - t[c];
        cls = fmaf(d, d, cls);
    }

    float b1x = p[20], b1y = p[21], b1w = p[22], b1h = p[23], b1c = p[24];
    float b2x = p[25], b2y = p[26], b2w = p[27], b2h = p[28], b2c = p[29];
    // tb = targets[..., C:C+5] -> channels 20..24 (channel 20 doubles as obj flag)
    float tx = t[20], ty = t[21], tw = t[22], th = t[23], tc = t[24];
    float obj = (t[20] == 1.0f) ? 1.0f : 0.0f;

    float iou1 = iou_fn(b1x, b1y, b1w, b1h, tx, ty, tw, th);
    float iou2 = iou_fn(b2x, b2y, b2w, b2h, tx, ty, tw, th);
    bool use1 = iou1 > iou2;

    float rx = use1 ? b1x : b2x;
    float ry = use1 ? b1y : b2y;
    float rw = use1 ? b1w : b2w;
    float rh = use1 ? b1h : b2h;
    float rc = use1 ? b1c : b2c;
    float other_conf = use1 ? b2c : b1c;

    float srw = sqrtf(fmaxf(rw, 1e-6f));
    float srh = sqrtf(fmaxf(rh, 1e-6f));
    float stw = sqrtf(fmaxf(tw, 1e-6f));
    float sth = sqrtf(fmaxf(th, 1e-6f));

    float dx = rx - tx, dy = ry - ty, dw = srw - stw, dh = srh - sth;
    float coord = 5.0f * (dx * dx + dy * dy + dw * dw + dh * dh);
    float dc = rc - tc;
    float obj_conf = dc * dc;
    float noobj_in  = 0.5f * other_conf * other_conf;
    float noobj_out = 0.5f * (b1c * b1c + b2c * b2c);

    return obj * (coord + obj_conf + cls + noobj_in) + (1.0f - obj) * noobj_out;
}

__global__ __launch_bounds__(CPB)
void yolo_loss_kernel(const float* __restrict__ pred,
                      const float* __restrict__ tgt,
                      float* __restrict__ out) {
    extern __shared__ __align__(128) float smem[];
    __shared__ __align__(8) unsigned long long mbar_store[NSTAGE];
    __shared__ float warp_sums[CPB / 32];

    const int tid = threadIdx.x;
    const int bid = blockIdx.x;
    const uint32_t sbase = (uint32_t)__cvta_generic_to_shared(smem);
    const uint32_t mb0   = (uint32_t)__cvta_generic_to_shared(mbar_store);

    // Balanced contiguous partition of tiles across blocks.
    const int q = NTILES / NBLK;           // 21
    const int r = NTILES % NBLK;           // 56
    const int start = bid * q + (bid < r ? bid : r);
    const int nt = q + (bid < r ? 1 : 0);  // 21 or 22

    if (tid == 0) {
        #pragma unroll
        for (int s = 0; s < NSTAGE; s++) mbar_init(mb0 + s * 8, 1);
    }
    __syncthreads();

    // Producer helper: issue tile j into stage slot (j % NSTAGE).
    auto issue = [&](int j) {
        const int s = j & (NSTAGE - 1);
        const uint32_t mb = mb0 + s * 8;
        const uint32_t dst = sbase + s * STAGE_B;
        mbar_expect_tx(mb, STAGE_B);
        bulk_g2s(dst, pred + (size_t)(start + j) * CPB * PREDC, PRED_TILE_B, mb);
        bulk_g2s(dst + PRED_TILE_B, tgt + (size_t)(start + j) * CPB * TGTC, TGT_TILE_B, mb);
    };

    // Prologue: prefetch depth NSTAGE-1.
    if (tid == 0) {
        for (int s = 0; s < NSTAGE - 1 && s < nt; s++) issue(s);
    }

    float acc = 0.0f;
    for (int i = 0; i < nt; i++) {
        mbar_wait(mb0 + (i & (NSTAGE - 1)) * 8, (i >> 2) & 1);  // tile i data ready
        __syncthreads();  // all threads finished reading tile i-1's slot ((i+3)&3)
        if (tid == 0 && i + NSTAGE - 1 < nt) issue(i + NSTAGE - 1);
        acc += compute_tile(smem + (size_t)(i & (NSTAGE - 1)) * (STAGE_B / 4), tid);
    }

    // Block reduce + single atomic.
    #pragma unroll
    for (int off = 16; off > 0; off >>= 1)
        acc += __shfl_xor_sync(0xFFFFFFFFu, acc, off);
    int lane = tid & 31, wid = tid >> 5;
    if (lane == 0) warp_sums[wid] = acc;
    __syncthreads();
    if (tid == 0) {
        float s = 0.0f;
        #pragma unroll
        for (int w = 0; w < CPB / 32; w++) s += warp_sums[w];
        atomicAdd(out, s * (1.0f / (float)BATCH));
    }
}

extern "C" void kernel_launch(void* const* d_in, const int* in_sizes, int n_in,
                              void* d_out, int out_size) {
    const float* pred = (const float*)d_in[0];
    const float* tgt  = (const float*)d_in[1];
    float* out = (float*)d_out;
    cudaFuncSetAttribute(yolo_loss_kernel,
                         cudaFuncAttributeMaxDynamicSharedMemorySize, SMEM_BYTES);
    cudaMemsetAsync(out, 0, sizeof(float));
    yolo_loss_kernel<<<NBLK, CPB, SMEM_BYTES>>>(pred, tgt, out);
}